// round 1
// baseline (speedup 1.0000x reference)
#include <cuda_runtime.h>

#define Bn   512
#define Sn   200
#define Dn   512
#define Hn   8
#define FFn  1024
#define EMBn 128
#define HIDn 1024
#define FINn 64
#define UD   1152        // D + 5*EMB
#define BS   (Bn*Sn)     // 102400

// ---------------- scratch (static device globals; no runtime allocation) ----
__device__ float g_x[(size_t)BS*Dn];       // embeddings -> later x_final
__device__ float g_qkv[(size_t)BS*3*Dn];   // qkv -> later attn_proj
__device__ float g_attn[(size_t)BS*Dn];    // attn raw out -> later f2
__device__ float g_xn[(size_t)BS*Dn];      // x after first LN chain
__device__ float g_h[(size_t)BS*FFn];      // FFN hidden
__device__ float g_mask[BS];
__device__ float g_u[Bn*UD];
__device__ float g_h2[Bn*HIDn];

// ---------------- embedding + mask ----------------
__global__ void embed_kernel(const int* __restrict__ seq, const float* __restrict__ tab)
{
    int i = blockIdx.x;           // 0..BS-1
    int t = threadIdx.x;          // 128 threads, one float4 each
    int item = seq[i];
    if (t == 0) g_mask[i] = (item == 0) ? 0.f : 1.f;
    float4 v = ((const float4*)(tab + (size_t)item * Dn))[t];
    v.x = fminf(fmaxf(v.x * 0.5f, -1.f), 1.f);
    v.y = fminf(fmaxf(v.y * 0.5f, -1.f), 1.f);
    v.z = fminf(fmaxf(v.z * 0.5f, -1.f), 1.f);
    v.w = fminf(fmaxf(v.w * 0.5f, -1.f), 1.f);
    ((float4*)(g_x + (size_t)i * Dn))[t] = v;
}

// ---------------- generic SGEMM: C[M,N] = epi(A[M,K] @ W[N,K]^T + bias) ------
// M must be a multiple of 128 (true for all call sites). N guarded.
__global__ __launch_bounds__(256) void gemm_nt(
    const float* __restrict__ A, const float* __restrict__ W,
    const float* __restrict__ bias, float* __restrict__ C,
    int M, int N, int K, float lo, float hi, int relu)
{
    __shared__ float As[16][128];
    __shared__ float Bs[16][128];
    int tid = threadIdx.x;
    int tx = tid & 15, ty = tid >> 4;
    int lrow = tid >> 2;             // 0..63
    int lc4  = (tid & 3) * 4;        // 0,4,8,12
    const float* Ab = A + (size_t)blockIdx.y * 128 * K;
    const float* Wb = W + (size_t)blockIdx.x * 128 * K;
    int nbase = blockIdx.x * 128;

    float acc[8][8];
#pragma unroll
    for (int i = 0; i < 8; i++)
#pragma unroll
        for (int j = 0; j < 8; j++) acc[i][j] = 0.f;

    for (int k0 = 0; k0 < K; k0 += 16) {
#pragma unroll
        for (int r = 0; r < 2; r++) {
            int row = lrow + r * 64;
            float4 a = *(const float4*)(Ab + (size_t)row * K + k0 + lc4);
            As[lc4+0][row] = a.x; As[lc4+1][row] = a.y;
            As[lc4+2][row] = a.z; As[lc4+3][row] = a.w;
            float4 w4 = make_float4(0.f, 0.f, 0.f, 0.f);
            if (nbase + row < N)
                w4 = *(const float4*)(Wb + (size_t)row * K + k0 + lc4);
            Bs[lc4+0][row] = w4.x; Bs[lc4+1][row] = w4.y;
            Bs[lc4+2][row] = w4.z; Bs[lc4+3][row] = w4.w;
        }
        __syncthreads();
#pragma unroll
        for (int kk = 0; kk < 16; kk++) {
            float af[8], bf[8];
            *(float4*)&af[0] = *(const float4*)&As[kk][ty*8];
            *(float4*)&af[4] = *(const float4*)&As[kk][ty*8+4];
            *(float4*)&bf[0] = *(const float4*)&Bs[kk][tx*8];
            *(float4*)&bf[4] = *(const float4*)&Bs[kk][tx*8+4];
#pragma unroll
            for (int i = 0; i < 8; i++)
#pragma unroll
                for (int j = 0; j < 8; j++)
                    acc[i][j] = fmaf(af[i], bf[j], acc[i][j]);
        }
        __syncthreads();
    }

    int row0 = blockIdx.y * 128 + ty * 8;
    int col0 = nbase + tx * 8;
#pragma unroll
    for (int i = 0; i < 8; i++) {
#pragma unroll
        for (int j = 0; j < 8; j++) {
            int c = col0 + j;
            if (c < N) {
                float v = acc[i][j] + (bias ? bias[c] : 0.f);
                v = fminf(fmaxf(v, lo), hi);
                if (relu) v = fmaxf(v, 0.f);
                C[(size_t)(row0 + i) * N + c] = v;
            }
        }
    }
}

// ---------------- fused attention per (b,h) --------------------------------
// scores clipped to [-3,3] before softmax => use fixed max = 3 (no online max).
__global__ __launch_bounds__(256) void attn_kernel()
{
    __shared__ float Ks[64][64];
    __shared__ float Vs[64][64];
    __shared__ float msk[64];
    int h = blockIdx.x, b = blockIdx.y;
    int tid = threadIdx.x;
    const float* base = g_qkv + (size_t)b * Sn * 1536;
    bool active = tid < Sn;

    float q[64], acc[64];
    float l = 0.f;
#pragma unroll
    for (int d = 0; d < 64; d++) acc[d] = 0.f;
    if (active) {
        const float4* qp = (const float4*)(base + (size_t)tid * 1536 + h * 64);
#pragma unroll
        for (int i = 0; i < 16; i++) ((float4*)q)[i] = qp[i];
    }

    for (int j0 = 0; j0 < Sn; j0 += 64) {
        __syncthreads();
        for (int idx = tid; idx < 1024; idx += 256) {
            int r = idx >> 4;
            int c = (idx & 15) * 4;
            float4 kv = make_float4(0.f, 0.f, 0.f, 0.f), vv = kv;
            if (j0 + r < Sn) {
                const float* rp = base + (size_t)(j0 + r) * 1536 + h * 64 + c;
                kv = *(const float4*)(rp + 512);
                vv = *(const float4*)(rp + 1024);
            }
            *(float4*)&Ks[r][c] = kv;
            *(float4*)&Vs[r][c] = vv;
        }
        if (tid < 64) msk[tid] = (j0 + tid < Sn) ? g_mask[b * Sn + j0 + tid] : 0.f;
        __syncthreads();
        if (active) {
            for (int j = 0; j < 64; j++) {
                float s = 0.f;
#pragma unroll
                for (int d = 0; d < 64; d++) s = fmaf(q[d], Ks[j][d], s);
                s = fminf(fmaxf(s * 2.5f, -3.f), 3.f);     // /(sqrt(64)*0.05) = *2.5, clip +-3
                float e = msk[j] * __expf(s - 3.f);         // masked -> 0
                l += e;
#pragma unroll
                for (int d = 0; d < 64; d++) acc[d] = fmaf(e, Vs[j][d], acc[d]);
            }
        }
    }
    if (active) {
        float inv = 1.f / l;
        float* op = g_attn + (size_t)(b * Sn + tid) * Dn + h * 64;
#pragma unroll
        for (int d = 0; d < 64; d++) op[d] = acc[d] * inv;
    }
}

// ---------------- fused double residual+LN ---------------------------------
__device__ __forceinline__ void block_reduce2(float& a, float& b, float* red)
{
    __syncthreads();
#pragma unroll
    for (int o = 16; o > 0; o >>= 1) {
        a += __shfl_xor_sync(0xffffffffu, a, o);
        b += __shfl_xor_sync(0xffffffffu, b, o);
    }
    int w = threadIdx.x >> 5;
    if ((threadIdx.x & 31) == 0) { red[w] = a; red[w + 8] = b; }
    __syncthreads();
    if (threadIdx.x == 0) {
        float ta = 0.f, tb = 0.f;
        for (int i = 0; i < 8; i++) { ta += red[i]; tb += red[i + 8]; }
        red[0] = ta; red[8] = tb;
    }
    __syncthreads();
    a = red[0]; b = red[8];
}

// out = LN(x + LN(x + p)); optional final clip
__global__ __launch_bounds__(256) void ln_chain_kernel(
    const float* __restrict__ x, const float* __restrict__ p,
    const float* __restrict__ g, const float* __restrict__ bt,
    float* __restrict__ out, float clipv)
{
    __shared__ float red[16];
    int row = blockIdx.x;
    int t = threadIdx.x;
    float2 xv = ((const float2*)(x + (size_t)row * Dn))[t];
    float2 pv = ((const float2*)(p + (size_t)row * Dn))[t];
    float t0 = xv.x + pv.x, t1 = xv.y + pv.y;
    float s1 = t0 + t1, s2 = t0 * t0 + t1 * t1;
    block_reduce2(s1, s2, red);
    float mean = s1 * (1.f / Dn);
    float inv = rsqrtf(s2 * (1.f / Dn) - mean * mean + 1e-6f);
    float2 gv = ((const float2*)g)[t];
    float2 bv = ((const float2*)bt)[t];
    float sa0 = (t0 - mean) * inv * gv.x + bv.x;
    float sa1 = (t1 - mean) * inv * gv.y + bv.y;
    float u0 = xv.x + sa0, u1 = xv.y + sa1;
    s1 = u0 + u1; s2 = u0 * u0 + u1 * u1;
    block_reduce2(s1, s2, red);
    mean = s1 * (1.f / Dn);
    inv = rsqrtf(s2 * (1.f / Dn) - mean * mean + 1e-6f);
    float o0 = (u0 - mean) * inv * gv.x + bv.x;
    float o1 = (u1 - mean) * inv * gv.y + bv.y;
    if (clipv > 0.f) {
        o0 = fminf(fmaxf(o0, -clipv), clipv);
        o1 = fminf(fmaxf(o1, -clipv), clipv);
    }
    ((float2*)(out + (size_t)row * Dn))[t] = make_float2(o0, o1);
}

// ---------------- masked mean pool + user feature concat --------------------
__global__ void pool_u_kernel(
    const float* __restrict__ uctr, const float* __restrict__ uti,
    const int* __restrict__ age, const int* __restrict__ gen, const int* __restrict__ cms,
    const float* __restrict__ atab, const float* __restrict__ gtab, const float* __restrict__ ctab,
    const float* __restrict__ cw, const float* __restrict__ cb,
    const float* __restrict__ tw, const float* __restrict__ tb)
{
    int b = blockIdx.x, j = threadIdx.x;   // 512 threads
    const float* base = g_x + (size_t)b * Sn * Dn;   // g_x holds clipped x_final
    float sum = 0.f, ms = 0.f;
    for (int s = 0; s < Sn; s++) {
        float m = g_mask[b * Sn + s];
        sum = fmaf(base[(size_t)s * Dn + j], m, sum);
        ms += m;
    }
    float rep = sum / (ms + 1e-8f);
    rep = fminf(fmaxf(rep, -5.f), 5.f);
    float* u = g_u + b * UD;
    u[j] = rep;
    if (j < EMBn) {
        u[512 + j]  = fmaf(uctr[b], cw[j], cb[j]);
        u[640 + j]  = fmaf(uti[b],  tw[j], tb[j]);
        u[768 + j]  = atab[age[b] * EMBn + j];
        u[896 + j]  = gtab[gen[b] * EMBn + j];
        u[1024 + j] = ctab[cms[b] * EMBn + j];
    }
}

// ---------------- launch ----------------------------------------------------
extern "C" void kernel_launch(void* const* d_in, const int* in_sizes, int n_in,
                              void* d_out, int out_size)
{
    const int*   item_seq = (const int*)d_in[0];
    const float* uctr = (const float*)d_in[1];
    const float* uti  = (const float*)d_in[2];
    const int*   age  = (const int*)d_in[3];
    const int*   gen  = (const int*)d_in[4];
    const int*   cms  = (const int*)d_in[5];
    const float* emb  = (const float*)d_in[6];
    const float* inw  = (const float*)d_in[7];
    const float* outw = (const float*)d_in[8];
    const float* outb = (const float*)d_in[9];
    const float* ln1g = (const float*)d_in[10];
    const float* ln1b = (const float*)d_in[11];
    const float* ln2g = (const float*)d_in[12];
    const float* ln2b = (const float*)d_in[13];
    const float* l1w  = (const float*)d_in[14];
    const float* l1b  = (const float*)d_in[15];
    const float* l2w  = (const float*)d_in[16];
    const float* l2b  = (const float*)d_in[17];
    const float* atab = (const float*)d_in[18];
    const float* gtab = (const float*)d_in[19];
    const float* ctab = (const float*)d_in[20];
    const float* cw   = (const float*)d_in[21];
    const float* cb   = (const float*)d_in[22];
    const float* tw   = (const float*)d_in[23];
    const float* tb   = (const float*)d_in[24];
    const float* m1w  = (const float*)d_in[25];
    const float* m1b  = (const float*)d_in[26];
    const float* m2w  = (const float*)d_in[27];
    const float* m2b  = (const float*)d_in[28];
    float* out = (float*)d_out;

    float *px, *pqkv, *pattn, *pxn, *ph, *pu, *ph2;
    cudaGetSymbolAddress((void**)&px,    g_x);
    cudaGetSymbolAddress((void**)&pqkv,  g_qkv);
    cudaGetSymbolAddress((void**)&pattn, g_attn);
    cudaGetSymbolAddress((void**)&pxn,   g_xn);
    cudaGetSymbolAddress((void**)&ph,    g_h);
    cudaGetSymbolAddress((void**)&pu,    g_u);
    cudaGetSymbolAddress((void**)&ph2,   g_h2);

    const float INF = 1e30f;

    // x = clip(emb*0.5), mask
    embed_kernel<<<BS, 128>>>(item_seq, emb);
    // qkv = clip(x @ in_proj^T, +-1)
    gemm_nt<<<dim3(12, 800), 256>>>(px, inw, nullptr, pqkv, BS, 1536, 512, -1.f, 1.f, 0);
    // fused softmax attention
    attn_kernel<<<dim3(Hn, Bn), 256>>>();
    // attn_proj = clip(attn @ out_w^T + b, +-3)   (reuse qkv buffer)
    gemm_nt<<<dim3(4, 800), 256>>>(pattn, outw, outb, pqkv, BS, 512, 512, -3.f, 3.f, 0);
    // x_new = LN(x + LN(x + attn_proj))
    ln_chain_kernel<<<BS, 256>>>(px, pqkv, ln1g, ln1b, pxn, 0.f);
    // h = relu(clip(x_new @ lin1^T + b, +-2))
    gemm_nt<<<dim3(8, 800), 256>>>(pxn, l1w, l1b, ph, BS, 1024, 512, -2.f, 2.f, 1);
    // f2 = clip(h @ lin2^T + b, +-2)   (reuse attn buffer)
    gemm_nt<<<dim3(4, 800), 256>>>(ph, l2w, l2b, pattn, BS, 512, 1024, -2.f, 2.f, 0);
    // x_final = clip(LN(x_new + LN(x_new + f2)), +-5)  -> g_x
    ln_chain_kernel<<<BS, 256>>>(pxn, pattn, ln2g, ln2b, px, 5.f);
    // seq_rep + user features -> u
    pool_u_kernel<<<Bn, 512>>>(uctr, uti, age, gen, cms, atab, gtab, ctab, cw, cb, tw, tb);
    // mlp head
    gemm_nt<<<dim3(8, 4), 256>>>(pu, m1w, m1b, ph2, Bn, HIDn, UD, -INF, INF, 1);
    gemm_nt<<<dim3(1, 4), 256>>>(ph2, m2w, m2b, out, Bn, FINn, HIDn, -INF, INF, 0);
}

// round 3
// speedup vs baseline: 2.0311x; 2.0311x over previous
#include <cuda_runtime.h>
#include <cstdint>

#define Bn   512
#define Sn   200
#define Dn   512
#define Hn   8
#define FFn  1024
#define EMBn 128
#define HIDn 1024
#define FINn 64
#define UD   1152        // D + 5*EMB
#define BS   (Bn*Sn)     // 102400

// ---------------- scratch (static device globals; no runtime allocation) ----
__device__ float g_x[(size_t)BS*Dn];       // embeddings -> later x_final
__device__ float g_qkv[(size_t)BS*3*Dn];   // qkv -> later attn_proj
__device__ float g_attn[(size_t)BS*Dn];    // attn raw out -> later f2
__device__ float g_xn[(size_t)BS*Dn];      // x after first LN chain
__device__ float g_h[(size_t)BS*FFn];      // FFN hidden
__device__ float g_mask[BS];
__device__ float g_u[Bn*UD];
__device__ float g_h2[Bn*HIDn];

__device__ __forceinline__ uint32_t f2tf32(float f) {
    uint32_t u;
    asm("cvt.rna.tf32.f32 %0, %1;" : "=r"(u) : "f"(f));
    return u;
}

// =================== tf32 mma.sync GEMM: C[M,N] = epi(A @ W^T + bias) =======
// CTA tile 128x128, BK=16. 8 warps (2 M x 4 N), warp tile 64x32.
// M, N multiples of 128; K multiple of 16.
#define PADK 20

__global__ __launch_bounds__(256) void mma_gemm(
    const float* __restrict__ A, const float* __restrict__ W,
    const float* __restrict__ bias, float* __restrict__ C,
    int N, int K, float lo, float hi, int relu)
{
    __shared__ uint32_t As[128][PADK];
    __shared__ uint32_t Bs[128][PADK];

    const int tid  = threadIdx.x;
    const int lane = tid & 31;
    const int wid  = tid >> 5;
    const int gid  = lane >> 2;      // group id (0..7)
    const int tig  = lane & 3;       // thread in group

    const int mw = (wid >> 2) * 64;  // warp M offset in tile
    const int nw = (wid & 3) * 32;   // warp N offset in tile

    const size_t rowA0 = (size_t)blockIdx.y * 128;
    const size_t rowW0 = (size_t)blockIdx.x * 128;

    // global->smem mapping: 512 float4 slots per operand tile; thread does 2
    const int r0 = tid >> 2;             // slot row for s = tid
    const int c0 = (tid & 3) << 2;       // float col (0,4,8,12)
    const int r1 = (tid + 256) >> 2;
    // c for second slot equals c0 (since +256 doesn't change tid&3)

    float acc[4][4][4];
#pragma unroll
    for (int mi = 0; mi < 4; mi++)
#pragma unroll
        for (int ni = 0; ni < 4; ni++)
#pragma unroll
            for (int j = 0; j < 4; j++) acc[mi][ni][j] = 0.f;

    const int nit = K >> 4;
    float4 pa0, pa1, pb0, pb1;

    // prefetch first tile
    pa0 = *(const float4*)(A + (rowA0 + r0) * K + c0);
    pa1 = *(const float4*)(A + (rowA0 + r1) * K + c0);
    pb0 = *(const float4*)(W + (rowW0 + r0) * K + c0);
    pb1 = *(const float4*)(W + (rowW0 + r1) * K + c0);

    for (int ck = 0; ck < nit; ck++) {
        // store prefetched tile to smem (tf32 converted)
        *(uint4*)&As[r0][c0] = make_uint4(f2tf32(pa0.x), f2tf32(pa0.y), f2tf32(pa0.z), f2tf32(pa0.w));
        *(uint4*)&As[r1][c0] = make_uint4(f2tf32(pa1.x), f2tf32(pa1.y), f2tf32(pa1.z), f2tf32(pa1.w));
        *(uint4*)&Bs[r0][c0] = make_uint4(f2tf32(pb0.x), f2tf32(pb0.y), f2tf32(pb0.z), f2tf32(pb0.w));
        *(uint4*)&Bs[r1][c0] = make_uint4(f2tf32(pb1.x), f2tf32(pb1.y), f2tf32(pb1.z), f2tf32(pb1.w));
        __syncthreads();

        if (ck + 1 < nit) {
            const int k0 = (ck + 1) << 4;
            pa0 = *(const float4*)(A + (rowA0 + r0) * K + k0 + c0);
            pa1 = *(const float4*)(A + (rowA0 + r1) * K + k0 + c0);
            pb0 = *(const float4*)(W + (rowW0 + r0) * K + k0 + c0);
            pb1 = *(const float4*)(W + (rowW0 + r1) * K + k0 + c0);
        }

#pragma unroll
        for (int kk = 0; kk < 16; kk += 8) {
            uint32_t af[4][4], bf[4][2];
#pragma unroll
            for (int mi = 0; mi < 4; mi++) {
                int r = mw + mi * 16 + gid;
                af[mi][0] = As[r][kk + tig];
                af[mi][1] = As[r + 8][kk + tig];
                af[mi][2] = As[r][kk + tig + 4];
                af[mi][3] = As[r + 8][kk + tig + 4];
            }
#pragma unroll
            for (int ni = 0; ni < 4; ni++) {
                int n = nw + ni * 8 + gid;
                bf[ni][0] = Bs[n][kk + tig];
                bf[ni][1] = Bs[n][kk + tig + 4];
            }
#pragma unroll
            for (int mi = 0; mi < 4; mi++)
#pragma unroll
                for (int ni = 0; ni < 4; ni++) {
                    asm volatile(
                        "mma.sync.aligned.m16n8k8.row.col.f32.tf32.tf32.f32 "
                        "{%0,%1,%2,%3}, {%4,%5,%6,%7}, {%8,%9}, {%0,%1,%2,%3};"
                        : "+f"(acc[mi][ni][0]), "+f"(acc[mi][ni][1]),
                          "+f"(acc[mi][ni][2]), "+f"(acc[mi][ni][3])
                        : "r"(af[mi][0]), "r"(af[mi][1]), "r"(af[mi][2]), "r"(af[mi][3]),
                          "r"(bf[ni][0]), "r"(bf[ni][1]));
                }
        }
        __syncthreads();
    }

    // epilogue
#pragma unroll
    for (int mi = 0; mi < 4; mi++) {
        size_t row = rowA0 + mw + mi * 16 + gid;
#pragma unroll
        for (int ni = 0; ni < 4; ni++) {
            int col = blockIdx.x * 128 + nw + ni * 8 + 2 * tig;
            float b0 = bias ? bias[col]     : 0.f;
            float b1 = bias ? bias[col + 1] : 0.f;
            float v0 = acc[mi][ni][0] + b0, v1 = acc[mi][ni][1] + b1;
            float v2 = acc[mi][ni][2] + b0, v3 = acc[mi][ni][3] + b1;
            v0 = fminf(fmaxf(v0, lo), hi); v1 = fminf(fmaxf(v1, lo), hi);
            v2 = fminf(fmaxf(v2, lo), hi); v3 = fminf(fmaxf(v3, lo), hi);
            if (relu) {
                v0 = fmaxf(v0, 0.f); v1 = fmaxf(v1, 0.f);
                v2 = fmaxf(v2, 0.f); v3 = fmaxf(v3, 0.f);
            }
            *(float2*)(C + row * N + col)       = make_float2(v0, v1);
            *(float2*)(C + (row + 8) * N + col) = make_float2(v2, v3);
        }
    }
}

// ---------------- embedding + mask ----------------
__global__ void embed_kernel(const int* __restrict__ seq, const float* __restrict__ tab)
{
    int i = blockIdx.x;
    int t = threadIdx.x;
    int item = seq[i];
    if (t == 0) g_mask[i] = (item == 0) ? 0.f : 1.f;
    float4 v = ((const float4*)(tab + (size_t)item * Dn))[t];
    v.x = fminf(fmaxf(v.x * 0.5f, -1.f), 1.f);
    v.y = fminf(fmaxf(v.y * 0.5f, -1.f), 1.f);
    v.z = fminf(fmaxf(v.z * 0.5f, -1.f), 1.f);
    v.w = fminf(fmaxf(v.w * 0.5f, -1.f), 1.f);
    ((float4*)(g_x + (size_t)i * Dn))[t] = v;
}

// ---------------- fp32 SIMT GEMM (small head GEMMs only) --------------------
__global__ __launch_bounds__(256) void gemm_nt(
    const float* __restrict__ A, const float* __restrict__ W,
    const float* __restrict__ bias, float* __restrict__ C,
    int M, int N, int K, float lo, float hi, int relu)
{
    __shared__ float As[16][128];
    __shared__ float Bs[16][128];
    int tid = threadIdx.x;
    int tx = tid & 15, ty = tid >> 4;
    int lrow = tid >> 2;
    int lc4  = (tid & 3) * 4;
    const float* Ab = A + (size_t)blockIdx.y * 128 * K;
    const float* Wb = W + (size_t)blockIdx.x * 128 * K;
    int nbase = blockIdx.x * 128;

    float acc[8][8];
#pragma unroll
    for (int i = 0; i < 8; i++)
#pragma unroll
        for (int j = 0; j < 8; j++) acc[i][j] = 0.f;

    for (int k0 = 0; k0 < K; k0 += 16) {
#pragma unroll
        for (int r = 0; r < 2; r++) {
            int row = lrow + r * 64;
            float4 a = *(const float4*)(Ab + (size_t)row * K + k0 + lc4);
            As[lc4+0][row] = a.x; As[lc4+1][row] = a.y;
            As[lc4+2][row] = a.z; As[lc4+3][row] = a.w;
            float4 w4 = make_float4(0.f, 0.f, 0.f, 0.f);
            if (nbase + row < N)
                w4 = *(const float4*)(Wb + (size_t)row * K + k0 + lc4);
            Bs[lc4+0][row] = w4.x; Bs[lc4+1][row] = w4.y;
            Bs[lc4+2][row] = w4.z; Bs[lc4+3][row] = w4.w;
        }
        __syncthreads();
#pragma unroll
        for (int kk = 0; kk < 16; kk++) {
            float af[8], bf[8];
            *(float4*)&af[0] = *(const float4*)&As[kk][ty*8];
            *(float4*)&af[4] = *(const float4*)&As[kk][ty*8+4];
            *(float4*)&bf[0] = *(const float4*)&Bs[kk][tx*8];
            *(float4*)&bf[4] = *(const float4*)&Bs[kk][tx*8+4];
#pragma unroll
            for (int i = 0; i < 8; i++)
#pragma unroll
                for (int j = 0; j < 8; j++)
                    acc[i][j] = fmaf(af[i], bf[j], acc[i][j]);
        }
        __syncthreads();
    }

    int row0 = blockIdx.y * 128 + ty * 8;
    int col0 = nbase + tx * 8;
#pragma unroll
    for (int i = 0; i < 8; i++) {
#pragma unroll
        for (int j = 0; j < 8; j++) {
            int c = col0 + j;
            if (c < N) {
                float v = acc[i][j] + (bias ? bias[c] : 0.f);
                v = fminf(fmaxf(v, lo), hi);
                if (relu) v = fmaxf(v, 0.f);
                C[(size_t)(row0 + i) * N + c] = v;
            }
        }
    }
}

// ---------------- fused attention per (b,h) --------------------------------
// scores clipped to [-3,3] before softmax => fixed max = 3 (no online max).
__global__ __launch_bounds__(256) void attn_kernel()
{
    __shared__ float Ks[64][64];
    __shared__ float Vs[64][64];
    __shared__ float msk[64];
    int h = blockIdx.x, b = blockIdx.y;
    int tid = threadIdx.x;
    const float* base = g_qkv + (size_t)b * Sn * 1536;
    bool active = tid < Sn;

    float q[64], acc[64];
    float l = 0.f;
#pragma unroll
    for (int d = 0; d < 64; d++) acc[d] = 0.f;
    if (active) {
        const float4* qp = (const float4*)(base + (size_t)tid * 1536 + h * 64);
#pragma unroll
        for (int i = 0; i < 16; i++) ((float4*)q)[i] = qp[i];
    }

    for (int j0 = 0; j0 < Sn; j0 += 64) {
        __syncthreads();
        for (int idx = tid; idx < 1024; idx += 256) {
            int r = idx >> 4;
            int c = (idx & 15) * 4;
            float4 kv = make_float4(0.f, 0.f, 0.f, 0.f), vv = kv;
            if (j0 + r < Sn) {
                const float* rp = base + (size_t)(j0 + r) * 1536 + h * 64 + c;
                kv = *(const float4*)(rp + 512);
                vv = *(const float4*)(rp + 1024);
            }
            *(float4*)&Ks[r][c] = kv;
            *(float4*)&Vs[r][c] = vv;
        }
        if (tid < 64) msk[tid] = (j0 + tid < Sn) ? g_mask[b * Sn + j0 + tid] : 0.f;
        __syncthreads();
        if (active) {
            for (int j = 0; j < 64; j++) {
                float s = 0.f;
#pragma unroll
                for (int d = 0; d < 64; d++) s = fmaf(q[d], Ks[j][d], s);
                s = fminf(fmaxf(s * 2.5f, -3.f), 3.f);
                float e = msk[j] * __expf(s - 3.f);
                l += e;
#pragma unroll
                for (int d = 0; d < 64; d++) acc[d] = fmaf(e, Vs[j][d], acc[d]);
            }
        }
    }
    if (active) {
        float inv = 1.f / l;
        float* op = g_attn + (size_t)(b * Sn + tid) * Dn + h * 64;
#pragma unroll
        for (int d = 0; d < 64; d++) op[d] = acc[d] * inv;
    }
}

// ---------------- fused double residual+LN ---------------------------------
__device__ __forceinline__ void block_reduce2(float& a, float& b, float* red)
{
    __syncthreads();
#pragma unroll
    for (int o = 16; o > 0; o >>= 1) {
        a += __shfl_xor_sync(0xffffffffu, a, o);
        b += __shfl_xor_sync(0xffffffffu, b, o);
    }
    int w = threadIdx.x >> 5;
    if ((threadIdx.x & 31) == 0) { red[w] = a; red[w + 8] = b; }
    __syncthreads();
    if (threadIdx.x == 0) {
        float ta = 0.f, tb = 0.f;
        for (int i = 0; i < 8; i++) { ta += red[i]; tb += red[i + 8]; }
        red[0] = ta; red[8] = tb;
    }
    __syncthreads();
    a = red[0]; b = red[8];
}

__global__ __launch_bounds__(256) void ln_chain_kernel(
    const float* __restrict__ x, const float* __restrict__ p,
    const float* __restrict__ g, const float* __restrict__ bt,
    float* __restrict__ out, float clipv)
{
    __shared__ float red[16];
    int row = blockIdx.x;
    int t = threadIdx.x;
    float2 xv = ((const float2*)(x + (size_t)row * Dn))[t];
    float2 pv = ((const float2*)(p + (size_t)row * Dn))[t];
    float t0 = xv.x + pv.x, t1 = xv.y + pv.y;
    float s1 = t0 + t1, s2 = t0 * t0 + t1 * t1;
    block_reduce2(s1, s2, red);
    float mean = s1 * (1.f / Dn);
    float inv = rsqrtf(s2 * (1.f / Dn) - mean * mean + 1e-6f);
    float2 gv = ((const float2*)g)[t];
    float2 bv = ((const float2*)bt)[t];
    float sa0 = (t0 - mean) * inv * gv.x + bv.x;
    float sa1 = (t1 - mean) * inv * gv.y + bv.y;
    float u0 = xv.x + sa0, u1 = xv.y + sa1;
    s1 = u0 + u1; s2 = u0 * u0 + u1 * u1;
    block_reduce2(s1, s2, red);
    mean = s1 * (1.f / Dn);
    inv = rsqrtf(s2 * (1.f / Dn) - mean * mean + 1e-6f);
    float o0 = (u0 - mean) * inv * gv.x + bv.x;
    float o1 = (u1 - mean) * inv * gv.y + bv.y;
    if (clipv > 0.f) {
        o0 = fminf(fmaxf(o0, -clipv), clipv);
        o1 = fminf(fmaxf(o1, -clipv), clipv);
    }
    ((float2*)(out + (size_t)row * Dn))[t] = make_float2(o0, o1);
}

// ---------------- masked mean pool + user feature concat --------------------
__global__ void pool_u_kernel(
    const float* __restrict__ uctr, const float* __restrict__ uti,
    const int* __restrict__ age, const int* __restrict__ gen, const int* __restrict__ cms,
    const float* __restrict__ atab, const float* __restrict__ gtab, const float* __restrict__ ctab,
    const float* __restrict__ cw, const float* __restrict__ cb,
    const float* __restrict__ tw, const float* __restrict__ tb)
{
    int b = blockIdx.x, j = threadIdx.x;
    const float* base = g_x + (size_t)b * Sn * Dn;
    float sum = 0.f, ms = 0.f;
    for (int s = 0; s < Sn; s++) {
        float m = g_mask[b * Sn + s];
        sum = fmaf(base[(size_t)s * Dn + j], m, sum);
        ms += m;
    }
    float rep = sum / (ms + 1e-8f);
    rep = fminf(fmaxf(rep, -5.f), 5.f);
    float* u = g_u + b * UD;
    u[j] = rep;
    if (j < EMBn) {
        u[512 + j]  = fmaf(uctr[b], cw[j], cb[j]);
        u[640 + j]  = fmaf(uti[b],  tw[j], tb[j]);
        u[768 + j]  = atab[age[b] * EMBn + j];
        u[896 + j]  = gtab[gen[b] * EMBn + j];
        u[1024 + j] = ctab[cms[b] * EMBn + j];
    }
}

// ---------------- launch ----------------------------------------------------
extern "C" void kernel_launch(void* const* d_in, const int* in_sizes, int n_in,
                              void* d_out, int out_size)
{
    const int*   item_seq = (const int*)d_in[0];
    const float* uctr = (const float*)d_in[1];
    const float* uti  = (const float*)d_in[2];
    const int*   age  = (const int*)d_in[3];
    const int*   gen  = (const int*)d_in[4];
    const int*   cms  = (const int*)d_in[5];
    const float* emb  = (const float*)d_in[6];
    const float* inw  = (const float*)d_in[7];
    const float* outw = (const float*)d_in[8];
    const float* outb = (const float*)d_in[9];
    const float* ln1g = (const float*)d_in[10];
    const float* ln1b = (const float*)d_in[11];
    const float* ln2g = (const float*)d_in[12];
    const float* ln2b = (const float*)d_in[13];
    const float* l1w  = (const float*)d_in[14];
    const float* l1b  = (const float*)d_in[15];
    const float* l2w  = (const float*)d_in[16];
    const float* l2b  = (const float*)d_in[17];
    const float* atab = (const float*)d_in[18];
    const float* gtab = (const float*)d_in[19];
    const float* ctab = (const float*)d_in[20];
    const float* cw   = (const float*)d_in[21];
    const float* cb   = (const float*)d_in[22];
    const float* tw   = (const float*)d_in[23];
    const float* tb   = (const float*)d_in[24];
    const float* m1w  = (const float*)d_in[25];
    const float* m1b  = (const float*)d_in[26];
    const float* m2w  = (const float*)d_in[27];
    const float* m2b  = (const float*)d_in[28];
    float* out = (float*)d_out;

    float *px, *pqkv, *pattn, *pxn, *ph, *pu, *ph2;
    cudaGetSymbolAddress((void**)&px,    g_x);
    cudaGetSymbolAddress((void**)&pqkv,  g_qkv);
    cudaGetSymbolAddress((void**)&pattn, g_attn);
    cudaGetSymbolAddress((void**)&pxn,   g_xn);
    cudaGetSymbolAddress((void**)&ph,    g_h);
    cudaGetSymbolAddress((void**)&pu,    g_u);
    cudaGetSymbolAddress((void**)&ph2,   g_h2);

    const float INF = 1e30f;

    // x = clip(emb*0.5), mask
    embed_kernel<<<BS, 128>>>(item_seq, emb);
    // qkv = clip(x @ in_proj^T, +-1)   [tf32 mma.sync]
    mma_gemm<<<dim3(12, 800), 256>>>(px, inw, nullptr, pqkv, 1536, 512, -1.f, 1.f, 0);
    // fused softmax attention
    attn_kernel<<<dim3(Hn, Bn), 256>>>();
    // attn_proj = clip(attn @ out_w^T + b, +-3)   (reuse qkv buffer)
    mma_gemm<<<dim3(4, 800), 256>>>(pattn, outw, outb, pqkv, 512, 512, -3.f, 3.f, 0);
    // x_new = LN(x + LN(x + attn_proj))
    ln_chain_kernel<<<BS, 256>>>(px, pqkv, ln1g, ln1b, pxn, 0.f);
    // h = relu(clip(x_new @ lin1^T + b, +-2))
    mma_gemm<<<dim3(8, 800), 256>>>(pxn, l1w, l1b, ph, 1024, 512, -2.f, 2.f, 1);
    // f2 = clip(h @ lin2^T + b, +-2)   (reuse attn buffer)
    mma_gemm<<<dim3(4, 800), 256>>>(ph, l2w, l2b, pattn, 512, 1024, -2.f, 2.f, 0);
    // x_final = clip(LN(x_new + LN(x_new + f2)), +-5)  -> g_x
    ln_chain_kernel<<<BS, 256>>>(pxn, pattn, ln2g, ln2b, px, 5.f);
    // seq_rep + user features -> u
    pool_u_kernel<<<Bn, 512>>>(uctr, uti, age, gen, cms, atab, gtab, ctab, cw, cb, tw, tb);
    // mlp head (tiny; fp32 SIMT)
    gemm_nt<<<dim3(8, 4), 256>>>(pu, m1w, m1b, ph2, Bn, HIDn, UD, -INF, INF, 1);
    gemm_nt<<<dim3(1, 4), 256>>>(ph2, m2w, m2b, out, Bn, FINn, HIDn, -INF, INF, 0);
}

// round 4
// speedup vs baseline: 2.5577x; 1.2593x over previous
#include <cuda_runtime.h>
#include <cuda_fp16.h>
#include <cstdint>

#define Bn   512
#define Sn   200
#define Dn   512
#define Hn   8
#define FFn  1024
#define EMBn 128
#define HIDn 1024
#define FINn 64
#define UD   1152        // D + 5*EMB
#define BS   (Bn*Sn)     // 102400

// ---------------- scratch (static device globals; no runtime allocation) ----
__device__ float g_x[(size_t)BS*Dn];       // embeddings -> later x_final
__device__ float g_qkv[(size_t)BS*3*Dn];   // qkv -> later attn_proj
__device__ float g_attn[(size_t)BS*Dn];    // attn raw out -> later f2
__device__ float g_xn[(size_t)BS*Dn];      // x after first LN chain
__device__ float g_h[(size_t)BS*FFn];      // FFN hidden
__device__ float g_mask[BS];
__device__ float g_u[Bn*UD];
__device__ float g_h2[Bn*HIDn];

__device__ __forceinline__ uint32_t pack_h2(float a, float b) {
    __half2 h = __floats2half2_rn(a, b);
    return *(uint32_t*)&h;
}

// =================== fp16 mma.sync GEMM: C[M,N] = epi(A @ W^T + bias) =======
// CTA tile 128x128, BK=16. 8 warps (2 M x 4 N), warp tile 64x32.
// M, N multiples of 128; K multiple of 16. Double-buffered smem, 1 sync/iter.
// Row stride 12 b32 (only 8 used) -> conflict-free fragment LDS.
#define PADK 12

__global__ __launch_bounds__(256) void mma_gemm(
    const float* __restrict__ A, const float* __restrict__ W,
    const float* __restrict__ bias, float* __restrict__ C,
    int N, int K, float lo, float hi, int relu)
{
    __shared__ uint32_t As[2][128][PADK];
    __shared__ uint32_t Bs[2][128][PADK];

    const int tid  = threadIdx.x;
    const int lane = tid & 31;
    const int wid  = tid >> 5;
    const int gid  = lane >> 2;      // group id (0..7)
    const int tig  = lane & 3;       // thread in group

    const int mw = (wid >> 2) * 64;  // warp M offset in tile
    const int nw = (wid & 3) * 32;   // warp N offset in tile

    const size_t rowA0 = (size_t)blockIdx.y * 128;
    const size_t rowW0 = (size_t)blockIdx.x * 128;

    // global->smem: 512 float4 slots per operand tile; each thread does 2
    const int r0 = tid >> 2;             // 0..63
    const int r1 = r0 + 64;
    const int c0 = (tid & 3) << 2;       // float col: 0,4,8,12
    const int cb = c0 >> 1;              // b32 (half2) col: 0,2,4,6

    float acc[4][4][4];
#pragma unroll
    for (int mi = 0; mi < 4; mi++)
#pragma unroll
        for (int ni = 0; ni < 4; ni++)
#pragma unroll
            for (int j = 0; j < 4; j++) acc[mi][ni][j] = 0.f;

    const int nit = K >> 4;
    float4 pa0, pa1, pb0, pb1;

    // prefetch tile 0
    pa0 = *(const float4*)(A + (rowA0 + r0) * K + c0);
    pa1 = *(const float4*)(A + (rowA0 + r1) * K + c0);
    pb0 = *(const float4*)(W + (rowW0 + r0) * K + c0);
    pb1 = *(const float4*)(W + (rowW0 + r1) * K + c0);

    for (int ck = 0; ck < nit; ck++) {
        const int buf = ck & 1;
        // store prefetched tile (fp32 -> half2)
        *(uint2*)&As[buf][r0][cb] = make_uint2(pack_h2(pa0.x, pa0.y), pack_h2(pa0.z, pa0.w));
        *(uint2*)&As[buf][r1][cb] = make_uint2(pack_h2(pa1.x, pa1.y), pack_h2(pa1.z, pa1.w));
        *(uint2*)&Bs[buf][r0][cb] = make_uint2(pack_h2(pb0.x, pb0.y), pack_h2(pb0.z, pb0.w));
        *(uint2*)&Bs[buf][r1][cb] = make_uint2(pack_h2(pb1.x, pb1.y), pack_h2(pb1.z, pb1.w));
        __syncthreads();

        if (ck + 1 < nit) {
            const int k0 = (ck + 1) << 4;
            pa0 = *(const float4*)(A + (rowA0 + r0) * K + k0 + c0);
            pa1 = *(const float4*)(A + (rowA0 + r1) * K + k0 + c0);
            pb0 = *(const float4*)(W + (rowW0 + r0) * K + k0 + c0);
            pb1 = *(const float4*)(W + (rowW0 + r1) * K + k0 + c0);
        }

        uint32_t af[4][4], bf[4][2];
#pragma unroll
        for (int mi = 0; mi < 4; mi++) {
            int r = mw + mi * 16 + gid;
            af[mi][0] = As[buf][r][tig];
            af[mi][1] = As[buf][r + 8][tig];
            af[mi][2] = As[buf][r][tig + 4];
            af[mi][3] = As[buf][r + 8][tig + 4];
        }
#pragma unroll
        for (int ni = 0; ni < 4; ni++) {
            int n = nw + ni * 8 + gid;
            bf[ni][0] = Bs[buf][n][tig];
            bf[ni][1] = Bs[buf][n][tig + 4];
        }
#pragma unroll
        for (int mi = 0; mi < 4; mi++)
#pragma unroll
            for (int ni = 0; ni < 4; ni++) {
                asm volatile(
                    "mma.sync.aligned.m16n8k16.row.col.f32.f16.f16.f32 "
                    "{%0,%1,%2,%3}, {%4,%5,%6,%7}, {%8,%9}, {%0,%1,%2,%3};"
                    : "+f"(acc[mi][ni][0]), "+f"(acc[mi][ni][1]),
                      "+f"(acc[mi][ni][2]), "+f"(acc[mi][ni][3])
                    : "r"(af[mi][0]), "r"(af[mi][1]), "r"(af[mi][2]), "r"(af[mi][3]),
                      "r"(bf[ni][0]), "r"(bf[ni][1]));
            }
        // no trailing sync: next iter writes the other buffer; re-write of this
        // buffer happens after the NEXT sync, which orders it after these reads.
    }

    // epilogue
#pragma unroll
    for (int mi = 0; mi < 4; mi++) {
        size_t row = rowA0 + mw + mi * 16 + gid;
#pragma unroll
        for (int ni = 0; ni < 4; ni++) {
            int col = blockIdx.x * 128 + nw + ni * 8 + 2 * tig;
            float b0 = bias ? bias[col]     : 0.f;
            float b1 = bias ? bias[col + 1] : 0.f;
            float v0 = acc[mi][ni][0] + b0, v1 = acc[mi][ni][1] + b1;
            float v2 = acc[mi][ni][2] + b0, v3 = acc[mi][ni][3] + b1;
            v0 = fminf(fmaxf(v0, lo), hi); v1 = fminf(fmaxf(v1, lo), hi);
            v2 = fminf(fmaxf(v2, lo), hi); v3 = fminf(fmaxf(v3, lo), hi);
            if (relu) {
                v0 = fmaxf(v0, 0.f); v1 = fmaxf(v1, 0.f);
                v2 = fmaxf(v2, 0.f); v3 = fmaxf(v3, 0.f);
            }
            *(float2*)(C + row * N + col)       = make_float2(v0, v1);
            *(float2*)(C + (row + 8) * N + col) = make_float2(v2, v3);
        }
    }
}

// ---------------- embedding + mask ----------------
__global__ void embed_kernel(const int* __restrict__ seq, const float* __restrict__ tab)
{
    int i = blockIdx.x;
    int t = threadIdx.x;
    int item = seq[i];
    if (t == 0) g_mask[i] = (item == 0) ? 0.f : 1.f;
    float4 v = ((const float4*)(tab + (size_t)item * Dn))[t];
    v.x = fminf(fmaxf(v.x * 0.5f, -1.f), 1.f);
    v.y = fminf(fmaxf(v.y * 0.5f, -1.f), 1.f);
    v.z = fminf(fmaxf(v.z * 0.5f, -1.f), 1.f);
    v.w = fminf(fmaxf(v.w * 0.5f, -1.f), 1.f);
    ((float4*)(g_x + (size_t)i * Dn))[t] = v;
}

// ---------------- fp32 SIMT GEMM (small head GEMMs only) --------------------
__global__ __launch_bounds__(256) void gemm_nt(
    const float* __restrict__ A, const float* __restrict__ W,
    const float* __restrict__ bias, float* __restrict__ C,
    int M, int N, int K, float lo, float hi, int relu)
{
    __shared__ float As[16][128];
    __shared__ float Bs[16][128];
    int tid = threadIdx.x;
    int tx = tid & 15, ty = tid >> 4;
    int lrow = tid >> 2;
    int lc4  = (tid & 3) * 4;
    const float* Ab = A + (size_t)blockIdx.y * 128 * K;
    const float* Wb = W + (size_t)blockIdx.x * 128 * K;
    int nbase = blockIdx.x * 128;

    float acc[8][8];
#pragma unroll
    for (int i = 0; i < 8; i++)
#pragma unroll
        for (int j = 0; j < 8; j++) acc[i][j] = 0.f;

    for (int k0 = 0; k0 < K; k0 += 16) {
#pragma unroll
        for (int r = 0; r < 2; r++) {
            int row = lrow + r * 64;
            float4 a = *(const float4*)(Ab + (size_t)row * K + k0 + lc4);
            As[lc4+0][row] = a.x; As[lc4+1][row] = a.y;
            As[lc4+2][row] = a.z; As[lc4+3][row] = a.w;
            float4 w4 = make_float4(0.f, 0.f, 0.f, 0.f);
            if (nbase + row < N)
                w4 = *(const float4*)(Wb + (size_t)row * K + k0 + lc4);
            Bs[lc4+0][row] = w4.x; Bs[lc4+1][row] = w4.y;
            Bs[lc4+2][row] = w4.z; Bs[lc4+3][row] = w4.w;
        }
        __syncthreads();
#pragma unroll
        for (int kk = 0; kk < 16; kk++) {
            float af[8], bf[8];
            *(float4*)&af[0] = *(const float4*)&As[kk][ty*8];
            *(float4*)&af[4] = *(const float4*)&As[kk][ty*8+4];
            *(float4*)&bf[0] = *(const float4*)&Bs[kk][tx*8];
            *(float4*)&bf[4] = *(const float4*)&Bs[kk][tx*8+4];
#pragma unroll
            for (int i = 0; i < 8; i++)
#pragma unroll
                for (int j = 0; j < 8; j++)
                    acc[i][j] = fmaf(af[i], bf[j], acc[i][j]);
        }
        __syncthreads();
    }

    int row0 = blockIdx.y * 128 + ty * 8;
    int col0 = nbase + tx * 8;
#pragma unroll
    for (int i = 0; i < 8; i++) {
#pragma unroll
        for (int j = 0; j < 8; j++) {
            int c = col0 + j;
            if (c < N) {
                float v = acc[i][j] + (bias ? bias[c] : 0.f);
                v = fminf(fmaxf(v, lo), hi);
                if (relu) v = fmaxf(v, 0.f);
                C[(size_t)(row0 + i) * N + c] = v;
            }
        }
    }
}

// ---------------- fused attention per (b,h) --------------------------------
// scores clipped to [-3,3] before softmax => fixed max = 3 (no online max).
__global__ __launch_bounds__(256) void attn_kernel()
{
    __shared__ float Ks[64][64];
    __shared__ float Vs[64][64];
    __shared__ float msk[64];
    int h = blockIdx.x, b = blockIdx.y;
    int tid = threadIdx.x;
    const float* base = g_qkv + (size_t)b * Sn * 1536;
    bool active = tid < Sn;

    float q[64], acc[64];
    float l = 0.f;
#pragma unroll
    for (int d = 0; d < 64; d++) acc[d] = 0.f;
    if (active) {
        const float4* qp = (const float4*)(base + (size_t)tid * 1536 + h * 64);
#pragma unroll
        for (int i = 0; i < 16; i++) ((float4*)q)[i] = qp[i];
    }

    for (int j0 = 0; j0 < Sn; j0 += 64) {
        __syncthreads();
        for (int idx = tid; idx < 1024; idx += 256) {
            int r = idx >> 4;
            int c = (idx & 15) * 4;
            float4 kv = make_float4(0.f, 0.f, 0.f, 0.f), vv = kv;
            if (j0 + r < Sn) {
                const float* rp = base + (size_t)(j0 + r) * 1536 + h * 64 + c;
                kv = *(const float4*)(rp + 512);
                vv = *(const float4*)(rp + 1024);
            }
            *(float4*)&Ks[r][c] = kv;
            *(float4*)&Vs[r][c] = vv;
        }
        if (tid < 64) msk[tid] = (j0 + tid < Sn) ? g_mask[b * Sn + j0 + tid] : 0.f;
        __syncthreads();
        if (active) {
            for (int j = 0; j < 64; j++) {
                float s = 0.f;
#pragma unroll
                for (int d = 0; d < 64; d++) s = fmaf(q[d], Ks[j][d], s);
                s = fminf(fmaxf(s * 2.5f, -3.f), 3.f);
                float e = msk[j] * __expf(s - 3.f);
                l += e;
#pragma unroll
                for (int d = 0; d < 64; d++) acc[d] = fmaf(e, Vs[j][d], acc[d]);
            }
        }
    }
    if (active) {
        float inv = 1.f / l;
        float* op = g_attn + (size_t)(b * Sn + tid) * Dn + h * 64;
#pragma unroll
        for (int d = 0; d < 64; d++) op[d] = acc[d] * inv;
    }
}

// ---------------- fused double residual+LN ---------------------------------
__device__ __forceinline__ void block_reduce2(float& a, float& b, float* red)
{
    __syncthreads();
#pragma unroll
    for (int o = 16; o > 0; o >>= 1) {
        a += __shfl_xor_sync(0xffffffffu, a, o);
        b += __shfl_xor_sync(0xffffffffu, b, o);
    }
    int w = threadIdx.x >> 5;
    if ((threadIdx.x & 31) == 0) { red[w] = a; red[w + 8] = b; }
    __syncthreads();
    if (threadIdx.x == 0) {
        float ta = 0.f, tb = 0.f;
        for (int i = 0; i < 8; i++) { ta += red[i]; tb += red[i + 8]; }
        red[0] = ta; red[8] = tb;
    }
    __syncthreads();
    a = red[0]; b = red[8];
}

__global__ __launch_bounds__(256) void ln_chain_kernel(
    const float* __restrict__ x, const float* __restrict__ p,
    const float* __restrict__ g, const float* __restrict__ bt,
    float* __restrict__ out, float clipv)
{
    __shared__ float red[16];
    int row = blockIdx.x;
    int t = threadIdx.x;
    float2 xv = ((const float2*)(x + (size_t)row * Dn))[t];
    float2 pv = ((const float2*)(p + (size_t)row * Dn))[t];
    float t0 = xv.x + pv.x, t1 = xv.y + pv.y;
    float s1 = t0 + t1, s2 = t0 * t0 + t1 * t1;
    block_reduce2(s1, s2, red);
    float mean = s1 * (1.f / Dn);
    float inv = rsqrtf(s2 * (1.f / Dn) - mean * mean + 1e-6f);
    float2 gv = ((const float2*)g)[t];
    float2 bv = ((const float2*)bt)[t];
    float sa0 = (t0 - mean) * inv * gv.x + bv.x;
    float sa1 = (t1 - mean) * inv * gv.y + bv.y;
    float u0 = xv.x + sa0, u1 = xv.y + sa1;
    s1 = u0 + u1; s2 = u0 * u0 + u1 * u1;
    block_reduce2(s1, s2, red);
    mean = s1 * (1.f / Dn);
    inv = rsqrtf(s2 * (1.f / Dn) - mean * mean + 1e-6f);
    float o0 = (u0 - mean) * inv * gv.x + bv.x;
    float o1 = (u1 - mean) * inv * gv.y + bv.y;
    if (clipv > 0.f) {
        o0 = fminf(fmaxf(o0, -clipv), clipv);
        o1 = fminf(fmaxf(o1, -clipv), clipv);
    }
    ((float2*)(out + (size_t)row * Dn))[t] = make_float2(o0, o1);
}

// ---------------- masked mean pool + user feature concat --------------------
__global__ void pool_u_kernel(
    const float* __restrict__ uctr, const float* __restrict__ uti,
    const int* __restrict__ age, const int* __restrict__ gen, const int* __restrict__ cms,
    const float* __restrict__ atab, const float* __restrict__ gtab, const float* __restrict__ ctab,
    const float* __restrict__ cw, const float* __restrict__ cb,
    const float* __restrict__ tw, const float* __restrict__ tb)
{
    int b = blockIdx.x, j = threadIdx.x;
    const float* base = g_x + (size_t)b * Sn * Dn;
    float sum = 0.f, ms = 0.f;
    for (int s = 0; s < Sn; s++) {
        float m = g_mask[b * Sn + s];
        sum = fmaf(base[(size_t)s * Dn + j], m, sum);
        ms += m;
    }
    float rep = sum / (ms + 1e-8f);
    rep = fminf(fmaxf(rep, -5.f), 5.f);
    float* u = g_u + b * UD;
    u[j] = rep;
    if (j < EMBn) {
        u[512 + j]  = fmaf(uctr[b], cw[j], cb[j]);
        u[640 + j]  = fmaf(uti[b],  tw[j], tb[j]);
        u[768 + j]  = atab[age[b] * EMBn + j];
        u[896 + j]  = gtab[gen[b] * EMBn + j];
        u[1024 + j] = ctab[cms[b] * EMBn + j];
    }
}

// ---------------- launch ----------------------------------------------------
extern "C" void kernel_launch(void* const* d_in, const int* in_sizes, int n_in,
                              void* d_out, int out_size)
{
    const int*   item_seq = (const int*)d_in[0];
    const float* uctr = (const float*)d_in[1];
    const float* uti  = (const float*)d_in[2];
    const int*   age  = (const int*)d_in[3];
    const int*   gen  = (const int*)d_in[4];
    const int*   cms  = (const int*)d_in[5];
    const float* emb  = (const float*)d_in[6];
    const float* inw  = (const float*)d_in[7];
    const float* outw = (const float*)d_in[8];
    const float* outb = (const float*)d_in[9];
    const float* ln1g = (const float*)d_in[10];
    const float* ln1b = (const float*)d_in[11];
    const float* ln2g = (const float*)d_in[12];
    const float* ln2b = (const float*)d_in[13];
    const float* l1w  = (const float*)d_in[14];
    const float* l1b  = (const float*)d_in[15];
    const float* l2w  = (const float*)d_in[16];
    const float* l2b  = (const float*)d_in[17];
    const float* atab = (const float*)d_in[18];
    const float* gtab = (const float*)d_in[19];
    const float* ctab = (const float*)d_in[20];
    const float* cw   = (const float*)d_in[21];
    const float* cb   = (const float*)d_in[22];
    const float* tw   = (const float*)d_in[23];
    const float* tb   = (const float*)d_in[24];
    const float* m1w  = (const float*)d_in[25];
    const float* m1b  = (const float*)d_in[26];
    const float* m2w  = (const float*)d_in[27];
    const float* m2b  = (const float*)d_in[28];
    float* out = (float*)d_out;

    float *px, *pqkv, *pattn, *pxn, *ph, *pu, *ph2;
    cudaGetSymbolAddress((void**)&px,    g_x);
    cudaGetSymbolAddress((void**)&pqkv,  g_qkv);
    cudaGetSymbolAddress((void**)&pattn, g_attn);
    cudaGetSymbolAddress((void**)&pxn,   g_xn);
    cudaGetSymbolAddress((void**)&ph,    g_h);
    cudaGetSymbolAddress((void**)&pu,    g_u);
    cudaGetSymbolAddress((void**)&ph2,   g_h2);

    const float INF = 1e30f;

    // x = clip(emb*0.5), mask
    embed_kernel<<<BS, 128>>>(item_seq, emb);
    // qkv = clip(x @ in_proj^T, +-1)   [fp16 mma.sync]
    mma_gemm<<<dim3(12, 800), 256>>>(px, inw, nullptr, pqkv, 1536, 512, -1.f, 1.f, 0);
    // fused softmax attention
    attn_kernel<<<dim3(Hn, Bn), 256>>>();
    // attn_proj = clip(attn @ out_w^T + b, +-3)   (reuse qkv buffer)
    mma_gemm<<<dim3(4, 800), 256>>>(pattn, outw, outb, pqkv, 512, 512, -3.f, 3.f, 0);
    // x_new = LN(x + LN(x + attn_proj))
    ln_chain_kernel<<<BS, 256>>>(px, pqkv, ln1g, ln1b, pxn, 0.f);
    // h = relu(clip(x_new @ lin1^T + b, +-2))
    mma_gemm<<<dim3(8, 800), 256>>>(pxn, l1w, l1b, ph, 1024, 512, -2.f, 2.f, 1);
    // f2 = clip(h @ lin2^T + b, +-2)   (reuse attn buffer)
    mma_gemm<<<dim3(4, 800), 256>>>(ph, l2w, l2b, pattn, 512, 1024, -2.f, 2.f, 0);
    // x_final = clip(LN(x_new + LN(x_new + f2)), +-5)  -> g_x
    ln_chain_kernel<<<BS, 256>>>(pxn, pattn, ln2g, ln2b, px, 5.f);
    // seq_rep + user features -> u
    pool_u_kernel<<<Bn, 512>>>(uctr, uti, age, gen, cms, atab, gtab, ctab, cw, cb, tw, tb);
    // mlp head (tiny; fp32 SIMT)
    gemm_nt<<<dim3(8, 4), 256>>>(pu, m1w, m1b, ph2, Bn, HIDn, UD, -INF, INF, 1);
    gemm_nt<<<dim3(1, 4), 256>>>(ph2, m2w, m2b, out, Bn, FINn, HIDn, -INF, INF, 0);
}

// round 5
// speedup vs baseline: 3.8441x; 1.5030x over previous
#include <cuda_runtime.h>
#include <cuda_fp16.h>
#include <cstdint>

#define Bn   512
#define Sn   200
#define Dn   512
#define Hn   8
#define FFn  1024
#define EMBn 128
#define HIDn 1024
#define FINn 64
#define UD   1152        // D + 5*EMB
#define BS   (Bn*Sn)     // 102400

// ---------------- scratch (static device globals; no runtime allocation) ----
__device__ float g_x[(size_t)BS*Dn];       // embeddings -> later x_final
__device__ float g_qkv[(size_t)BS*3*Dn];   // qkv -> later attn_proj
__device__ float g_attn[(size_t)BS*Dn];    // attn raw out -> later f2
__device__ float g_xn[(size_t)BS*Dn];      // x after first LN chain
__device__ float g_h[(size_t)BS*FFn];      // FFN hidden
__device__ float g_mask[BS];
__device__ float g_u[Bn*UD];
__device__ float g_h2[Bn*HIDn];

__device__ __forceinline__ uint32_t pack_h2(float a, float b) {
    __half2 h = __floats2half2_rn(a, b);
    return *(uint32_t*)&h;
}

__device__ __forceinline__ void mma16816(float* c,
    uint32_t a0, uint32_t a1, uint32_t a2, uint32_t a3,
    uint32_t b0, uint32_t b1)
{
    asm volatile(
        "mma.sync.aligned.m16n8k16.row.col.f32.f16.f16.f32 "
        "{%0,%1,%2,%3}, {%4,%5,%6,%7}, {%8,%9}, {%0,%1,%2,%3};"
        : "+f"(c[0]), "+f"(c[1]), "+f"(c[2]), "+f"(c[3])
        : "r"(a0), "r"(a1), "r"(a2), "r"(a3), "r"(b0), "r"(b1));
}

// =================== fp16 mma.sync GEMM: C[M,N] = epi(A @ W^T + bias) =======
// CTA tile 128x128, BK=16. 8 warps (2 M x 4 N), warp tile 64x32.
#define PADK 12

__global__ __launch_bounds__(256) void mma_gemm(
    const float* __restrict__ A, const float* __restrict__ W,
    const float* __restrict__ bias, float* __restrict__ C,
    int N, int K, float lo, float hi, int relu)
{
    __shared__ uint32_t As[2][128][PADK];
    __shared__ uint32_t Bs[2][128][PADK];

    const int tid  = threadIdx.x;
    const int lane = tid & 31;
    const int wid  = tid >> 5;
    const int gid  = lane >> 2;
    const int tig  = lane & 3;

    const int mw = (wid >> 2) * 64;
    const int nw = (wid & 3) * 32;

    const size_t rowA0 = (size_t)blockIdx.y * 128;
    const size_t rowW0 = (size_t)blockIdx.x * 128;

    const int r0 = tid >> 2;
    const int r1 = r0 + 64;
    const int c0 = (tid & 3) << 2;
    const int cb = c0 >> 1;

    float acc[4][4][4];
#pragma unroll
    for (int mi = 0; mi < 4; mi++)
#pragma unroll
        for (int ni = 0; ni < 4; ni++)
#pragma unroll
            for (int j = 0; j < 4; j++) acc[mi][ni][j] = 0.f;

    const int nit = K >> 4;
    float4 pa0, pa1, pb0, pb1;

    pa0 = *(const float4*)(A + (rowA0 + r0) * K + c0);
    pa1 = *(const float4*)(A + (rowA0 + r1) * K + c0);
    pb0 = *(const float4*)(W + (rowW0 + r0) * K + c0);
    pb1 = *(const float4*)(W + (rowW0 + r1) * K + c0);

    for (int ck = 0; ck < nit; ck++) {
        const int buf = ck & 1;
        *(uint2*)&As[buf][r0][cb] = make_uint2(pack_h2(pa0.x, pa0.y), pack_h2(pa0.z, pa0.w));
        *(uint2*)&As[buf][r1][cb] = make_uint2(pack_h2(pa1.x, pa1.y), pack_h2(pa1.z, pa1.w));
        *(uint2*)&Bs[buf][r0][cb] = make_uint2(pack_h2(pb0.x, pb0.y), pack_h2(pb0.z, pb0.w));
        *(uint2*)&Bs[buf][r1][cb] = make_uint2(pack_h2(pb1.x, pb1.y), pack_h2(pb1.z, pb1.w));
        __syncthreads();

        if (ck + 1 < nit) {
            const int k0 = (ck + 1) << 4;
            pa0 = *(const float4*)(A + (rowA0 + r0) * K + k0 + c0);
            pa1 = *(const float4*)(A + (rowA0 + r1) * K + k0 + c0);
            pb0 = *(const float4*)(W + (rowW0 + r0) * K + k0 + c0);
            pb1 = *(const float4*)(W + (rowW0 + r1) * K + k0 + c0);
        }

        uint32_t af[4][4], bf[4][2];
#pragma unroll
        for (int mi = 0; mi < 4; mi++) {
            int r = mw + mi * 16 + gid;
            af[mi][0] = As[buf][r][tig];
            af[mi][1] = As[buf][r + 8][tig];
            af[mi][2] = As[buf][r][tig + 4];
            af[mi][3] = As[buf][r + 8][tig + 4];
        }
#pragma unroll
        for (int ni = 0; ni < 4; ni++) {
            int n = nw + ni * 8 + gid;
            bf[ni][0] = Bs[buf][n][tig];
            bf[ni][1] = Bs[buf][n][tig + 4];
        }
#pragma unroll
        for (int mi = 0; mi < 4; mi++)
#pragma unroll
            for (int ni = 0; ni < 4; ni++)
                mma16816(acc[mi][ni], af[mi][0], af[mi][1], af[mi][2], af[mi][3],
                         bf[ni][0], bf[ni][1]);
    }

#pragma unroll
    for (int mi = 0; mi < 4; mi++) {
        size_t row = rowA0 + mw + mi * 16 + gid;
#pragma unroll
        for (int ni = 0; ni < 4; ni++) {
            int col = blockIdx.x * 128 + nw + ni * 8 + 2 * tig;
            float b0 = bias ? bias[col]     : 0.f;
            float b1 = bias ? bias[col + 1] : 0.f;
            float v0 = acc[mi][ni][0] + b0, v1 = acc[mi][ni][1] + b1;
            float v2 = acc[mi][ni][2] + b0, v3 = acc[mi][ni][3] + b1;
            v0 = fminf(fmaxf(v0, lo), hi); v1 = fminf(fmaxf(v1, lo), hi);
            v2 = fminf(fmaxf(v2, lo), hi); v3 = fminf(fmaxf(v3, lo), hi);
            if (relu) {
                v0 = fmaxf(v0, 0.f); v1 = fmaxf(v1, 0.f);
                v2 = fmaxf(v2, 0.f); v3 = fmaxf(v3, 0.f);
            }
            *(float2*)(C + row * N + col)       = make_float2(v0, v1);
            *(float2*)(C + (row + 8) * N + col) = make_float2(v2, v3);
        }
    }
}

// =================== tensor-core attention per (b,h) ========================
// S=200 padded to 208. Fixed-max softmax (scores clipped to +-3).
#define SP 208
#define QK_STRIDE 36      // b32 per Q/K row (32 used + 4 pad)
#define P_STRIDE 108      // b32 per P/Vt row (104 used + 4 pad)
#define OFF_Q 44928       // halfs
#define OFF_K 59904       // halfs
#define OFF_VT 44928      // halfs (reuses Q region)
#define SMEM_HALFS 74880
#define ATTN_SMEM (SMEM_HALFS*2 + SP*4*2)   // 151424 bytes

__global__ __launch_bounds__(256) void attn_mma_kernel()
{
    extern __shared__ __half sm[];
    float* linv = (float*)(sm + SMEM_HALFS);
    float* msk  = linv + SP;
    uint32_t* P2 = (uint32_t*)sm;
    uint32_t* Q2 = (uint32_t*)(sm + OFF_Q);
    uint32_t* K2 = (uint32_t*)(sm + OFF_K);
    uint32_t* V2 = (uint32_t*)(sm + OFF_VT);

    const int h = blockIdx.x, b = blockIdx.y;
    const int tid = threadIdx.x;
    const int lane = tid & 31, wid = tid >> 5;
    const int gid = lane >> 2, tig = lane & 3;
    const float* base = g_qkv + (size_t)b * Sn * 1536 + h * 64;

    // ---- load Q, K (fp32 -> half2), mask ----
    for (int idx = tid; idx < SP * 32; idx += 256) {
        int row = idx >> 5, c2 = idx & 31;
        uint32_t pq = 0u, pk = 0u;
        if (row < Sn) {
            const float* rp = base + (size_t)row * 1536 + c2 * 2;
            float2 q = *(const float2*)rp;
            float2 k = *(const float2*)(rp + 512);
            pq = pack_h2(q.x, q.y);
            pk = pack_h2(k.x, k.y);
        }
        Q2[row * QK_STRIDE + c2] = pq;
        K2[row * QK_STRIDE + c2] = pk;
    }
    if (tid < SP) msk[tid] = (tid < Sn) ? g_mask[b * Sn + tid] : 0.f;
    __syncthreads();

    // ---- phase A: P = msk * exp(clip(2.5*QK^T, +-3) - 3), fp16 in smem ----
    for (int mt = wid; mt < 13; mt += 8) {
        int r = mt * 16 + gid;
        uint32_t af[4][4];
#pragma unroll
        for (int kc = 0; kc < 4; kc++) {
            af[kc][0] = Q2[r * QK_STRIDE + kc * 8 + tig];
            af[kc][1] = Q2[(r + 8) * QK_STRIDE + kc * 8 + tig];
            af[kc][2] = Q2[r * QK_STRIDE + kc * 8 + tig + 4];
            af[kc][3] = Q2[(r + 8) * QK_STRIDE + kc * 8 + tig + 4];
        }
        for (int nt = 0; nt < 26; nt++) {
            float sacc[4] = {0.f, 0.f, 0.f, 0.f};
            int n = nt * 8 + gid;
#pragma unroll
            for (int kc = 0; kc < 4; kc++) {
                uint32_t b0 = K2[n * QK_STRIDE + kc * 8 + tig];
                uint32_t b1 = K2[n * QK_STRIDE + kc * 8 + tig + 4];
                mma16816(sacc, af[kc][0], af[kc][1], af[kc][2], af[kc][3], b0, b1);
            }
            int c = nt * 8 + 2 * tig;
            float m0 = msk[c], m1 = msk[c + 1];
            float e0 = m0 * __expf(fminf(fmaxf(sacc[0] * 2.5f, -3.f), 3.f) - 3.f);
            float e1 = m1 * __expf(fminf(fmaxf(sacc[1] * 2.5f, -3.f), 3.f) - 3.f);
            float e2 = m0 * __expf(fminf(fmaxf(sacc[2] * 2.5f, -3.f), 3.f) - 3.f);
            float e3 = m1 * __expf(fminf(fmaxf(sacc[3] * 2.5f, -3.f), 3.f) - 3.f);
            P2[r * P_STRIDE + nt * 4 + tig]       = pack_h2(e0, e1);
            P2[(r + 8) * P_STRIDE + nt * 4 + tig] = pack_h2(e2, e3);
        }
    }
    __syncthreads();

    // ---- load V transposed (Vt[d][key], overwrites Q region) + row sums ----
    for (int idx = tid; idx < SP * 64; idx += 256) {
        int row = idx >> 6, col = idx & 63;
        float v = (row < Sn) ? base[(size_t)row * 1536 + 1024 + col] : 0.f;
        sm[OFF_VT + col * (2 * P_STRIDE) + row] = __float2half(v);
    }
    for (int t = tid; t < SP; t += 256) {
        float s = 0.f;
        for (int i = 0; i < 104; i++) {
            __half2 hv = *(__half2*)&P2[t * P_STRIDE + i];
            float2 f = __half22float2(hv);
            s += f.x + f.y;
        }
        linv[t] = 1.f / s;
    }
    __syncthreads();

    // ---- phase B: O = (P @ Vt^T) * linv ----
    for (int mt = wid; mt < 13; mt += 8) {
        int r = mt * 16 + gid;
        float acc[8][4];
#pragma unroll
        for (int nt = 0; nt < 8; nt++)
#pragma unroll
            for (int j = 0; j < 4; j++) acc[nt][j] = 0.f;

        for (int kc = 0; kc < 13; kc++) {
            uint32_t a0 = P2[r * P_STRIDE + kc * 8 + tig];
            uint32_t a1 = P2[(r + 8) * P_STRIDE + kc * 8 + tig];
            uint32_t a2 = P2[r * P_STRIDE + kc * 8 + tig + 4];
            uint32_t a3 = P2[(r + 8) * P_STRIDE + kc * 8 + tig + 4];
#pragma unroll
            for (int nt = 0; nt < 8; nt++) {
                int d = nt * 8 + gid;
                uint32_t b0 = V2[d * P_STRIDE + kc * 8 + tig];
                uint32_t b1 = V2[d * P_STRIDE + kc * 8 + tig + 4];
                mma16816(acc[nt], a0, a1, a2, a3, b0, b1);
            }
        }
        float i0 = linv[r];
        float i1 = linv[r + 8];
        if (r < Sn) {
            float* op = g_attn + (size_t)(b * Sn + r) * Dn + h * 64 + 2 * tig;
#pragma unroll
            for (int nt = 0; nt < 8; nt++)
                *(float2*)(op + nt * 8) = make_float2(acc[nt][0] * i0, acc[nt][1] * i0);
        }
        if (r + 8 < Sn) {
            float* op = g_attn + (size_t)(b * Sn + r + 8) * Dn + h * 64 + 2 * tig;
#pragma unroll
            for (int nt = 0; nt < 8; nt++)
                *(float2*)(op + nt * 8) = make_float2(acc[nt][2] * i1, acc[nt][3] * i1);
        }
    }
}

// ---------------- embedding + mask ----------------
__global__ void embed_kernel(const int* __restrict__ seq, const float* __restrict__ tab)
{
    int i = blockIdx.x;
    int t = threadIdx.x;
    int item = seq[i];
    if (t == 0) g_mask[i] = (item == 0) ? 0.f : 1.f;
    float4 v = ((const float4*)(tab + (size_t)item * Dn))[t];
    v.x = fminf(fmaxf(v.x * 0.5f, -1.f), 1.f);
    v.y = fminf(fmaxf(v.y * 0.5f, -1.f), 1.f);
    v.z = fminf(fmaxf(v.z * 0.5f, -1.f), 1.f);
    v.w = fminf(fmaxf(v.w * 0.5f, -1.f), 1.f);
    ((float4*)(g_x + (size_t)i * Dn))[t] = v;
}

// ---------------- fp32 SIMT GEMM (small head GEMMs only) --------------------
__global__ __launch_bounds__(256) void gemm_nt(
    const float* __restrict__ A, const float* __restrict__ W,
    const float* __restrict__ bias, float* __restrict__ C,
    int M, int N, int K, float lo, float hi, int relu)
{
    __shared__ float As[16][128];
    __shared__ float Bs[16][128];
    int tid = threadIdx.x;
    int tx = tid & 15, ty = tid >> 4;
    int lrow = tid >> 2;
    int lc4  = (tid & 3) * 4;
    const float* Ab = A + (size_t)blockIdx.y * 128 * K;
    const float* Wb = W + (size_t)blockIdx.x * 128 * K;
    int nbase = blockIdx.x * 128;

    float acc[8][8];
#pragma unroll
    for (int i = 0; i < 8; i++)
#pragma unroll
        for (int j = 0; j < 8; j++) acc[i][j] = 0.f;

    for (int k0 = 0; k0 < K; k0 += 16) {
#pragma unroll
        for (int r = 0; r < 2; r++) {
            int row = lrow + r * 64;
            float4 a = *(const float4*)(Ab + (size_t)row * K + k0 + lc4);
            As[lc4+0][row] = a.x; As[lc4+1][row] = a.y;
            As[lc4+2][row] = a.z; As[lc4+3][row] = a.w;
            float4 w4 = make_float4(0.f, 0.f, 0.f, 0.f);
            if (nbase + row < N)
                w4 = *(const float4*)(Wb + (size_t)row * K + k0 + lc4);
            Bs[lc4+0][row] = w4.x; Bs[lc4+1][row] = w4.y;
            Bs[lc4+2][row] = w4.z; Bs[lc4+3][row] = w4.w;
        }
        __syncthreads();
#pragma unroll
        for (int kk = 0; kk < 16; kk++) {
            float af[8], bf[8];
            *(float4*)&af[0] = *(const float4*)&As[kk][ty*8];
            *(float4*)&af[4] = *(const float4*)&As[kk][ty*8+4];
            *(float4*)&bf[0] = *(const float4*)&Bs[kk][tx*8];
            *(float4*)&bf[4] = *(const float4*)&Bs[kk][tx*8+4];
#pragma unroll
            for (int i = 0; i < 8; i++)
#pragma unroll
                for (int j = 0; j < 8; j++)
                    acc[i][j] = fmaf(af[i], bf[j], acc[i][j]);
        }
        __syncthreads();
    }

    int row0 = blockIdx.y * 128 + ty * 8;
    int col0 = nbase + tx * 8;
#pragma unroll
    for (int i = 0; i < 8; i++) {
#pragma unroll
        for (int j = 0; j < 8; j++) {
            int c = col0 + j;
            if (c < N) {
                float v = acc[i][j] + (bias ? bias[c] : 0.f);
                v = fminf(fmaxf(v, lo), hi);
                if (relu) v = fmaxf(v, 0.f);
                C[(size_t)(row0 + i) * N + c] = v;
            }
        }
    }
}

// ---------------- fused double residual+LN ---------------------------------
__device__ __forceinline__ void block_reduce2(float& a, float& b, float* red)
{
    __syncthreads();
#pragma unroll
    for (int o = 16; o > 0; o >>= 1) {
        a += __shfl_xor_sync(0xffffffffu, a, o);
        b += __shfl_xor_sync(0xffffffffu, b, o);
    }
    int w = threadIdx.x >> 5;
    if ((threadIdx.x & 31) == 0) { red[w] = a; red[w + 8] = b; }
    __syncthreads();
    if (threadIdx.x == 0) {
        float ta = 0.f, tb = 0.f;
        for (int i = 0; i < 8; i++) { ta += red[i]; tb += red[i + 8]; }
        red[0] = ta; red[8] = tb;
    }
    __syncthreads();
    a = red[0]; b = red[8];
}

__global__ __launch_bounds__(256) void ln_chain_kernel(
    const float* __restrict__ x, const float* __restrict__ p,
    const float* __restrict__ g, const float* __restrict__ bt,
    float* __restrict__ out, float clipv)
{
    __shared__ float red[16];
    int row = blockIdx.x;
    int t = threadIdx.x;
    float2 xv = ((const float2*)(x + (size_t)row * Dn))[t];
    float2 pv = ((const float2*)(p + (size_t)row * Dn))[t];
    float t0 = xv.x + pv.x, t1 = xv.y + pv.y;
    float s1 = t0 + t1, s2 = t0 * t0 + t1 * t1;
    block_reduce2(s1, s2, red);
    float mean = s1 * (1.f / Dn);
    float inv = rsqrtf(s2 * (1.f / Dn) - mean * mean + 1e-6f);
    float2 gv = ((const float2*)g)[t];
    float2 bv = ((const float2*)bt)[t];
    float sa0 = (t0 - mean) * inv * gv.x + bv.x;
    float sa1 = (t1 - mean) * inv * gv.y + bv.y;
    float u0 = xv.x + sa0, u1 = xv.y + sa1;
    s1 = u0 + u1; s2 = u0 * u0 + u1 * u1;
    block_reduce2(s1, s2, red);
    mean = s1 * (1.f / Dn);
    inv = rsqrtf(s2 * (1.f / Dn) - mean * mean + 1e-6f);
    float o0 = (u0 - mean) * inv * gv.x + bv.x;
    float o1 = (u1 - mean) * inv * gv.y + bv.y;
    if (clipv > 0.f) {
        o0 = fminf(fmaxf(o0, -clipv), clipv);
        o1 = fminf(fmaxf(o1, -clipv), clipv);
    }
    ((float2*)(out + (size_t)row * Dn))[t] = make_float2(o0, o1);
}

// ---------------- masked mean pool + user feature concat --------------------
__global__ void pool_u_kernel(
    const float* __restrict__ uctr, const float* __restrict__ uti,
    const int* __restrict__ age, const int* __restrict__ gen, const int* __restrict__ cms,
    const float* __restrict__ atab, const float* __restrict__ gtab, const float* __restrict__ ctab,
    const float* __restrict__ cw, const float* __restrict__ cb,
    const float* __restrict__ tw, const float* __restrict__ tb)
{
    int b = blockIdx.x, j = threadIdx.x;
    const float* base = g_x + (size_t)b * Sn * Dn;
    float sum = 0.f, ms = 0.f;
    for (int s = 0; s < Sn; s++) {
        float m = g_mask[b * Sn + s];
        sum = fmaf(base[(size_t)s * Dn + j], m, sum);
        ms += m;
    }
    float rep = sum / (ms + 1e-8f);
    rep = fminf(fmaxf(rep, -5.f), 5.f);
    float* u = g_u + b * UD;
    u[j] = rep;
    if (j < EMBn) {
        u[512 + j]  = fmaf(uctr[b], cw[j], cb[j]);
        u[640 + j]  = fmaf(uti[b],  tw[j], tb[j]);
        u[768 + j]  = atab[age[b] * EMBn + j];
        u[896 + j]  = gtab[gen[b] * EMBn + j];
        u[1024 + j] = ctab[cms[b] * EMBn + j];
    }
}

// ---------------- launch ----------------------------------------------------
extern "C" void kernel_launch(void* const* d_in, const int* in_sizes, int n_in,
                              void* d_out, int out_size)
{
    const int*   item_seq = (const int*)d_in[0];
    const float* uctr = (const float*)d_in[1];
    const float* uti  = (const float*)d_in[2];
    const int*   age  = (const int*)d_in[3];
    const int*   gen  = (const int*)d_in[4];
    const int*   cms  = (const int*)d_in[5];
    const float* emb  = (const float*)d_in[6];
    const float* inw  = (const float*)d_in[7];
    const float* outw = (const float*)d_in[8];
    const float* outb = (const float*)d_in[9];
    const float* ln1g = (const float*)d_in[10];
    const float* ln1b = (const float*)d_in[11];
    const float* ln2g = (const float*)d_in[12];
    const float* ln2b = (const float*)d_in[13];
    const float* l1w  = (const float*)d_in[14];
    const float* l1b  = (const float*)d_in[15];
    const float* l2w  = (const float*)d_in[16];
    const float* l2b  = (const float*)d_in[17];
    const float* atab = (const float*)d_in[18];
    const float* gtab = (const float*)d_in[19];
    const float* ctab = (const float*)d_in[20];
    const float* cw   = (const float*)d_in[21];
    const float* cb   = (const float*)d_in[22];
    const float* tw   = (const float*)d_in[23];
    const float* tb   = (const float*)d_in[24];
    const float* m1w  = (const float*)d_in[25];
    const float* m1b  = (const float*)d_in[26];
    const float* m2w  = (const float*)d_in[27];
    const float* m2b  = (const float*)d_in[28];
    float* out = (float*)d_out;

    float *px, *pqkv, *pattn, *pxn, *ph, *pu, *ph2;
    cudaGetSymbolAddress((void**)&px,    g_x);
    cudaGetSymbolAddress((void**)&pqkv,  g_qkv);
    cudaGetSymbolAddress((void**)&pattn, g_attn);
    cudaGetSymbolAddress((void**)&pxn,   g_xn);
    cudaGetSymbolAddress((void**)&ph,    g_h);
    cudaGetSymbolAddress((void**)&pu,    g_u);
    cudaGetSymbolAddress((void**)&ph2,   g_h2);

    cudaFuncSetAttribute(attn_mma_kernel,
                         cudaFuncAttributeMaxDynamicSharedMemorySize, ATTN_SMEM);

    const float INF = 1e30f;

    // x = clip(emb*0.5), mask
    embed_kernel<<<BS, 128>>>(item_seq, emb);
    // qkv = clip(x @ in_proj^T, +-1)   [fp16 mma.sync]
    mma_gemm<<<dim3(12, 800), 256>>>(px, inw, nullptr, pqkv, 1536, 512, -1.f, 1.f, 0);
    // tensor-core softmax attention
    attn_mma_kernel<<<dim3(Hn, Bn), 256, ATTN_SMEM>>>();
    // attn_proj = clip(attn @ out_w^T + b, +-3)   (reuse qkv buffer)
    mma_gemm<<<dim3(4, 800), 256>>>(pattn, outw, outb, pqkv, 512, 512, -3.f, 3.f, 0);
    // x_new = LN(x + LN(x + attn_proj))
    ln_chain_kernel<<<BS, 256>>>(px, pqkv, ln1g, ln1b, pxn, 0.f);
    // h = relu(clip(x_new @ lin1^T + b, +-2))
    mma_gemm<<<dim3(8, 800), 256>>>(pxn, l1w, l1b, ph, 1024, 512, -2.f, 2.f, 1);
    // f2 = clip(h @ lin2^T + b, +-2)   (reuse attn buffer)
    mma_gemm<<<dim3(4, 800), 256>>>(ph, l2w, l2b, pattn, 512, 1024, -2.f, 2.f, 0);
    // x_final = clip(LN(x_new + LN(x_new + f2)), +-5)  -> g_x
    ln_chain_kernel<<<BS, 256>>>(pxn, pattn, ln2g, ln2b, px, 5.f);
    // seq_rep + user features -> u
    pool_u_kernel<<<Bn, 512>>>(uctr, uti, age, gen, cms, atab, gtab, ctab, cw, cb, tw, tb);
    // mlp head (tiny; fp32 SIMT)
    gemm_nt<<<dim3(8, 4), 256>>>(pu, m1w, m1b, ph2, Bn, HIDn, UD, -INF, INF, 1);
    gemm_nt<<<dim3(1, 4), 256>>>(ph2, m2w, m2b, out, Bn, FINn, HIDn, -INF, INF, 0);
}